// round 6
// baseline (speedup 1.0000x reference)
#include <cuda_runtime.h>
#include <cstdint>

// ---------------- problem constants ----------------
#define DDIM    64
#define MTOT    1024
#define NTRAIN  4096
#define TM      128                // CTA M tile (test rows)
#define TN      64                 // CTA N tile (train rows)
#define NSPLIT  (NTRAIN / TN)      // 64
#define MT      (MTOT / TM)        // 8
#define CC      901.6844f          // log2(e)/var, var = 0.0016
#define HS      450.8422f          // 0.5*CC
#define INVCC   (1.0f / 901.6844f)

// deterministic cross-block scratch (transposed: [m][split]) + counters
__device__ float g_scratch[MTOT * NSPLIT];
__device__ int   g_cnt[MT];

struct SmemT {
    alignas(1024) unsigned char A[TM * 128];   // bf16 [row][64], SW128
    alignas(1024) unsigned char B[TN * 128];   // bf16 [row][64], SW128
    float hsa[TM];     // HS * ||a||^2 (exact fp32)
    float hsb[TN];     // HS * ||b||^2
    float red[2][TM];
};

__device__ __forceinline__ uint32_t smem_u32(const void* p) {
    return (uint32_t)__cvta_generic_to_shared(p);
}
__device__ __forceinline__ uint32_t bf16x2_pack(float lo, float hi) {
    uint32_t r;
    asm("cvt.rn.bf16x2.f32 %0, %1, %2;" : "=r"(r) : "f"(hi), "f"(lo));
    return r;
}
__device__ __forceinline__ float ex2f(float x) {
    float y; asm("ex2.approx.f32 %0, %1;" : "=f"(y) : "f"(x)); return y;
}
__device__ __forceinline__ uint32_t sw128(uint32_t o) {
    return o ^ ((o >> 3) & 0x70);
}
__device__ __forceinline__ void ldsm4(uint32_t r[4], uint32_t addr) {
    asm volatile("ldmatrix.sync.aligned.m8n8.x4.shared.b16 {%0,%1,%2,%3}, [%4];"
                 : "=r"(r[0]), "=r"(r[1]), "=r"(r[2]), "=r"(r[3]) : "r"(addr));
}
__device__ __forceinline__ void mma16816(float d[4], const uint32_t a[4],
                                         uint32_t b0, uint32_t b1) {
    asm volatile("mma.sync.aligned.m16n8k16.row.col.f32.bf16.bf16.f32 "
                 "{%0,%1,%2,%3}, {%4,%5,%6,%7}, {%8,%9}, {%0,%1,%2,%3};"
                 : "+f"(d[0]), "+f"(d[1]), "+f"(d[2]), "+f"(d[3])
                 : "r"(a[0]), "r"(a[1]), "r"(a[2]), "r"(a[3]),
                   "r"(b0), "r"(b1));
}

__global__ __launch_bounds__(256, 3)
void kde_mma(const float* __restrict__ test_x,
             const float* __restrict__ train_x,
             float* __restrict__ out)
{
    __shared__ SmemT smem;
    __shared__ int is_last;

    const int tid = threadIdx.x;
    const int wid = tid >> 5;
    const int lid = tid & 31;
    const int m0  = blockIdx.x * TM;
    const int n0  = blockIdx.y * TN;

    // ---- Single merged convert phase: all global loads issue together ----
    {
        const float4* ta = (const float4*)(test_x + (size_t)m0 * DDIM);
        const float4* tb = (const float4*)(train_x + (size_t)n0 * DDIM);
        #pragma unroll
        for (int i = 0; i < 8; i++) {          // A: 128 rows
            int idx = i * 256 + tid;
            int row = idx >> 4, j = idx & 15;
            float4 v = ta[idx];
            float s = v.x*v.x + v.y*v.y + v.z*v.z + v.w*v.w;
            s += __shfl_xor_sync(~0u, s, 8);
            s += __shfl_xor_sync(~0u, s, 4);
            s += __shfl_xor_sync(~0u, s, 2);
            s += __shfl_xor_sync(~0u, s, 1);
            if ((tid & 15) == 0) smem.hsa[row] = HS * s;
            uint32_t o = sw128((uint32_t)(row * 128 + j * 8));
            *(uint2*)(smem.A + o) = make_uint2(bf16x2_pack(v.x, v.y),
                                               bf16x2_pack(v.z, v.w));
        }
        #pragma unroll
        for (int i = 0; i < 4; i++) {          // B: 64 rows
            int idx = i * 256 + tid;
            int row = idx >> 4, j = idx & 15;
            float4 v = tb[idx];
            float s = v.x*v.x + v.y*v.y + v.z*v.z + v.w*v.w;
            s += __shfl_xor_sync(~0u, s, 8);
            s += __shfl_xor_sync(~0u, s, 4);
            s += __shfl_xor_sync(~0u, s, 2);
            s += __shfl_xor_sync(~0u, s, 1);
            if ((tid & 15) == 0) smem.hsb[row] = HS * s;
            uint32_t o = sw128((uint32_t)(row * 128 + j * 8));
            *(uint2*)(smem.B + o) = make_uint2(bf16x2_pack(v.x, v.y),
                                               bf16x2_pack(v.z, v.w));
        }
    }
    __syncthreads();

    // ---- Warp tiling: warp (mw, nwp) owns rows mw*32..+31, cols nwp*32..+31 ----
    const int mw  = wid & 3;
    const int nwp = wid >> 2;            // 0..1
    const int g   = lid >> 2;
    const int tk  = lid & 3;
    const uint32_t baseA = smem_u32(smem.A);
    const uint32_t baseB = smem_u32(smem.B);

    // Per-warp conservative flush threshold (exact: exp2(x)=0 in fp32 for x<=-150)
    float thr;
    {
        float mna = smem.hsa[mw * 32 + lid];
        float mnb = smem.hsb[nwp * 32 + lid];
        #pragma unroll
        for (int s = 16; s; s >>= 1) {
            mna = fminf(mna, __shfl_xor_sync(~0u, mna, s));
            mnb = fminf(mnb, __shfl_xor_sync(~0u, mnb, s));
        }
        thr = (mna + mnb - 151.0f) * INVCC;   // d <= thr  =>  all exp2 == 0
    }

    uint32_t aAddr[4], bAddr[4];
    {
        int arow = mw * 32 + (lid & 7) + ((lid >> 3) & 1) * 8;
        int acol = (lid >> 4) * 16;
        #pragma unroll
        for (int ks = 0; ks < 4; ks++)
            aAddr[ks] = baseA + sw128((uint32_t)(arow * 128 + ks * 32 + acol));
        int brow = nwp * 32 + ((lid >> 4) & 1) * 8 + (lid & 7);
        int bcol = ((lid >> 3) & 1) * 16;
        #pragma unroll
        for (int ks = 0; ks < 4; ks++)
            bAddr[ks] = baseB + sw128((uint32_t)(brow * 128 + ks * 32 + bcol));
    }

    float acc[2][2] = {{0.f, 0.f}, {0.f, 0.f}};   // [mt][row-half]

    #pragma unroll
    for (int mt = 0; mt < 2; mt++) {          // m-subtiles sequential (regs!)
        uint32_t aF[4][4];
        #pragma unroll
        for (int ks = 0; ks < 4; ks++)
            ldsm4(aF[ks], aAddr[ks] + (uint32_t)mt * 2048);   // +16 rows, swizzle-safe

        #pragma unroll
        for (int p = 0; p < 2; p++) {         // 2 pairs of 8-col chunks
            uint32_t bF[4][4];
            #pragma unroll
            for (int ks = 0; ks < 4; ks++)
                ldsm4(bF[ks], bAddr[ks] + (uint32_t)p * 2048);

            float d[2][4] = {{0.f,0.f,0.f,0.f},{0.f,0.f,0.f,0.f}};
            #pragma unroll
            for (int ks = 0; ks < 4; ks++) {
                mma16816(d[0], aF[ks], bF[ks][0], bF[ks][1]);
                mma16816(d[1], aF[ks], bF[ks][2], bF[ks][3]);
            }

            float mx = d[0][0];
            #pragma unroll
            for (int c = 0; c < 2; c++)
                #pragma unroll
                for (int q = 0; q < 4; q++) mx = fmaxf(mx, d[c][q]);

            if (mx > thr) {   // rare exact path
                const int rb = mw * 32 + mt * 16 + g;
                const int cb = nwp * 32 + p * 16;
                float hra0 = smem.hsa[rb], hra1 = smem.hsa[rb + 8];
                float2 hb0 = *(const float2*)&smem.hsb[cb + tk * 2];
                float2 hb1 = *(const float2*)&smem.hsb[cb + 8 + tk * 2];
                #pragma unroll
                for (int c = 0; c < 2; c++) {
                    float hbx = c ? hb1.x : hb0.x;
                    float hby = c ? hb1.y : hb0.y;
                    acc[mt][0] += ex2f(fmaf(d[c][0], CC, -(hra0 + hbx)))
                                + ex2f(fmaf(d[c][1], CC, -(hra0 + hby)));
                    acc[mt][1] += ex2f(fmaf(d[c][2], CC, -(hra1 + hbx)))
                                + ex2f(fmaf(d[c][3], CC, -(hra1 + hby)));
                }
            }
        }
    }

    // ---- reduce across the 4 col-pair lanes; stash per-(nwp) row sums ----
    #pragma unroll
    for (int mt = 0; mt < 2; mt++)
        #pragma unroll
        for (int rr = 0; rr < 2; rr++) {
            float v = acc[mt][rr];
            v += __shfl_xor_sync(~0u, v, 1);
            v += __shfl_xor_sync(~0u, v, 2);
            acc[mt][rr] = v;
        }
    if (tk == 0) {
        #pragma unroll
        for (int mt = 0; mt < 2; mt++) {
            smem.red[nwp][mw * 32 + mt * 16 + g]     = acc[mt][0];
            smem.red[nwp][mw * 32 + mt * 16 + g + 8] = acc[mt][1];
        }
    }
    __syncthreads();

    // transposed scratch write: [m][split]
    if (tid < TM)
        g_scratch[(size_t)(m0 + tid) * NSPLIT + blockIdx.y] =
            smem.red[0][tid] + smem.red[1][tid];

    // ---- last block per m-tile: deterministic final reduction ----
    if (tid == 0) {
        __threadfence();
        int old = atomicAdd(&g_cnt[blockIdx.x], 1);
        is_last = (old == NSPLIT - 1);
        if (is_last) g_cnt[blockIdx.x] = 0;   // reset for graph replay
    }
    __syncthreads();
    if (is_last) {
        __threadfence();
        if (tid < TM) {
            const float4* pr = (const float4*)&g_scratch[(size_t)(m0 + tid) * NSPLIT];
            float s = 0.f;
            #pragma unroll
            for (int j = 0; j < NSPLIT / 4; j++) {   // 16 LDG.128
                float4 v = pr[j];
                s += (v.x + v.y) + (v.z + v.w);
            }
            out[m0 + tid] = s * (9.973557010f / 4096.0f);  // rsqrt(2*pi*var)/N
        }
    }
}

extern "C" void kernel_launch(void* const* d_in, const int* in_sizes, int n_in,
                              void* d_out, int out_size)
{
    const float* test_x  = (const float*)d_in[0];   // [1024,64]
    const float* train_x = (const float*)d_in[1];   // [4096,64]
    float* out = (float*)d_out;                     // [1024]

    dim3 grid(MT, NSPLIT);   // (8,64) = 512 CTAs, ~1.15 waves @ occ 3
    kde_mma<<<grid, 256>>>(test_x, train_x, out);
}

// round 7
// speedup vs baseline: 1.2179x; 1.2179x over previous
#include <cuda_runtime.h>
#include <cstdint>

// ---------------- problem constants ----------------
#define DDIM    64
#define MTOT    1024
#define NTRAIN  4096
#define TM      128                // CTA M tile
#define TN      128                // CTA N tile
#define NSPLIT  (NTRAIN / TN)      // 32
#define MT      (MTOT / TM)        // 8
#define CC      901.6844f          // log2(e)/var, var = 0.0016
#define HS      450.8422f          // 0.5*CC
#define INVCC   (1.0f / 901.6844f)

// ---------------- device-global staging ----------------
__device__ uint4 g_abf[MTOT   * 8];   // bf16 rows: 8 uint4 (128B) per row
__device__ uint4 g_bbf[NTRAIN * 8];
__device__ float g_hsa[MTOT];         // HS * ||a||^2 (exact fp32)
__device__ float g_hsb[NTRAIN];       // HS * ||b||^2
__device__ float g_scratch[MTOT * NSPLIT];   // [m][split]
__device__ int   g_cnt[MT];

struct SmemT {
    alignas(1024) unsigned char A[TM * 128];   // bf16 [row][64], SW128
    alignas(1024) unsigned char B[TN * 128];
    float hsa[TM];
    float hsb[TN];
    float red[2][TM];
};

__device__ __forceinline__ uint32_t smem_u32(const void* p) {
    return (uint32_t)__cvta_generic_to_shared(p);
}
__device__ __forceinline__ uint32_t bf16x2_pack(float lo, float hi) {
    uint32_t r;
    asm("cvt.rn.bf16x2.f32 %0, %1, %2;" : "=r"(r) : "f"(hi), "f"(lo));
    return r;
}
__device__ __forceinline__ float ex2f(float x) {
    float y; asm("ex2.approx.f32 %0, %1;" : "=f"(y) : "f"(x)); return y;
}
__device__ __forceinline__ uint32_t sw128(uint32_t o) {
    return o ^ ((o >> 3) & 0x70);
}
__device__ __forceinline__ void ldsm4(uint32_t r[4], uint32_t addr) {
    asm volatile("ldmatrix.sync.aligned.m8n8.x4.shared.b16 {%0,%1,%2,%3}, [%4];"
                 : "=r"(r[0]), "=r"(r[1]), "=r"(r[2]), "=r"(r[3]) : "r"(addr));
}
__device__ __forceinline__ void mma16816(float d[4], const uint32_t a[4],
                                         uint32_t b0, uint32_t b1) {
    asm volatile("mma.sync.aligned.m16n8k16.row.col.f32.bf16.bf16.f32 "
                 "{%0,%1,%2,%3}, {%4,%5,%6,%7}, {%8,%9}, {%0,%1,%2,%3};"
                 : "+f"(d[0]), "+f"(d[1]), "+f"(d[2]), "+f"(d[3])
                 : "r"(a[0]), "r"(a[1]), "r"(a[2]), "r"(a[3]),
                   "r"(b0), "r"(b1));
}

// ---- Kernel 1: one-shot fp32->bf16 conversion + norms (8 threads/row) ----
__global__ __launch_bounds__(256)
void kde_prep(const float* __restrict__ test_x,
              const float* __restrict__ train_x)
{
    const int gid = blockIdx.x * 256 + threadIdx.x;   // 0..40959
    const int row = gid >> 3;                         // 0..5119
    const int j   = gid & 7;                          // 8-float chunk
    const bool isA = (row < MTOT);
    const int  r   = isA ? row : row - MTOT;
    const float4* src = (const float4*)((isA ? test_x : train_x) + (size_t)r * DDIM);

    float4 v0 = src[j * 2];
    float4 v1 = src[j * 2 + 1];
    float s = v0.x*v0.x + v0.y*v0.y + v0.z*v0.z + v0.w*v0.w
            + v1.x*v1.x + v1.y*v1.y + v1.z*v1.z + v1.w*v1.w;
    s += __shfl_xor_sync(~0u, s, 1);
    s += __shfl_xor_sync(~0u, s, 2);
    s += __shfl_xor_sync(~0u, s, 4);
    if (j == 0) (isA ? g_hsa : g_hsb)[r] = HS * s;

    uint4 o = make_uint4(bf16x2_pack(v0.x, v0.y), bf16x2_pack(v0.z, v0.w),
                         bf16x2_pack(v1.x, v1.y), bf16x2_pack(v1.z, v1.w));
    (isA ? g_abf : g_bbf)[r * 8 + j] = o;
}

// ---- Kernel 2: MMA GEMM + fused deterministic reduction ----
__global__ __launch_bounds__(256, 2)
void kde_mma(float* __restrict__ out)
{
    __shared__ SmemT smem;
    __shared__ int is_last;

    const int tid = threadIdx.x;
    const int wid = tid >> 5;
    const int lid = tid & 31;
    const int m0  = blockIdx.x * TM;
    const int n0  = blockIdx.y * TN;

    // ---- Stage tiles: pure LDG.128 -> swizzled STS.128 (no conversion) ----
    #pragma unroll
    for (int i = 0; i < 4; i++) {                  // A: 1024 uint4
        int idx = i * 256 + tid;
        uint4 v = g_abf[m0 * 8 + idx];
        uint32_t o = sw128((uint32_t)(idx * 16));  // row*128 + jj*16
        *(uint4*)(smem.A + o) = v;
    }
    #pragma unroll
    for (int i = 0; i < 4; i++) {                  // B: 1024 uint4
        int idx = i * 256 + tid;
        uint4 v = g_bbf[n0 * 8 + idx];
        uint32_t o = sw128((uint32_t)(idx * 16));
        *(uint4*)(smem.B + o) = v;
    }
    if (tid < TM) smem.hsa[tid] = g_hsa[m0 + tid];
    smem.hsb[(tid & 127)] = g_hsb[n0 + (tid & 127)];   // 2x redundant write, benign
    __syncthreads();

    // ---- Warp tiling: warp (mw, nw) owns rows mw*32..+31, cols nw*64..+63 ----
    const int mw = wid & 3;
    const int nw = wid >> 2;
    const int g  = lid >> 2;
    const int tk = lid & 3;
    const uint32_t baseA = smem_u32(smem.A);
    const uint32_t baseB = smem_u32(smem.B);

    // Per-warp conservative flush threshold (exact: exp2(x)=0 in fp32, x<=-150)
    float thr;
    {
        float va = smem.hsa[mw * 32 + lid];
        float vb = fminf(smem.hsb[nw * 64 + lid], smem.hsb[nw * 64 + 32 + lid]);
        #pragma unroll
        for (int s = 16; s; s >>= 1) {
            va = fminf(va, __shfl_xor_sync(~0u, va, s));
            vb = fminf(vb, __shfl_xor_sync(~0u, vb, s));
        }
        thr = (va + vb - 151.0f) * INVCC;   // d <= thr  =>  whole pair flushes
    }

    // A fragments resident for the whole warp tile
    uint32_t aF[2][4][4];
    {
        int arow = mw * 32 + (lid & 7) + ((lid >> 3) & 1) * 8;
        int acol = (lid >> 4) * 16;
        #pragma unroll
        for (int mt = 0; mt < 2; mt++)
            #pragma unroll
            for (int ks = 0; ks < 4; ks++)
                ldsm4(aF[mt][ks],
                      baseA + sw128((uint32_t)((arow + mt * 16) * 128 + ks * 32 + acol)));
    }
    uint32_t bAddr4[4];
    {
        int rowb = nw * 64 + ((lid >> 4) & 1) * 8 + (lid & 7);
        int colb = ((lid >> 3) & 1) * 16;
        #pragma unroll
        for (int ks = 0; ks < 4; ks++)
            bAddr4[ks] = baseB + sw128((uint32_t)(rowb * 128 + ks * 32 + colb));
    }

    float hra[2][2];
    #pragma unroll
    for (int mt = 0; mt < 2; mt++) {
        hra[mt][0] = smem.hsa[mw * 32 + mt * 16 + g];
        hra[mt][1] = smem.hsa[mw * 32 + mt * 16 + g + 8];
    }

    float acc[2][2] = {{0.f, 0.f}, {0.f, 0.f}};

    #pragma unroll
    for (int p = 0; p < 4; p++) {                 // 4 pairs of 8-col chunks
        const uint32_t boff = (uint32_t)p * 2048; // +16 rows; swizzle-invariant
        uint32_t bF[4][4];
        #pragma unroll
        for (int ks = 0; ks < 4; ks++)
            ldsm4(bF[ks], bAddr4[ks] + boff);

        float d[2][2][4];
        #pragma unroll
        for (int mt = 0; mt < 2; mt++)
            #pragma unroll
            for (int c = 0; c < 2; c++)
                #pragma unroll
                for (int q = 0; q < 4; q++) d[mt][c][q] = 0.f;

        #pragma unroll
        for (int ks = 0; ks < 4; ks++)
            #pragma unroll
            for (int mt = 0; mt < 2; mt++) {
                mma16816(d[mt][0], aF[mt][ks], bF[ks][0], bF[ks][1]);
                mma16816(d[mt][1], aF[mt][ks], bF[ks][2], bF[ks][3]);
            }

        // pairwise max tree (depth 4) over the 16 raw dot values
        float m01 = fmaxf(fmaxf(d[0][0][0], d[0][0][1]), fmaxf(d[0][0][2], d[0][0][3]));
        float m23 = fmaxf(fmaxf(d[0][1][0], d[0][1][1]), fmaxf(d[0][1][2], d[0][1][3]));
        float m45 = fmaxf(fmaxf(d[1][0][0], d[1][0][1]), fmaxf(d[1][0][2], d[1][0][3]));
        float m67 = fmaxf(fmaxf(d[1][1][0], d[1][1][1]), fmaxf(d[1][1][2], d[1][1][3]));
        float mx  = fmaxf(fmaxf(m01, m23), fmaxf(m45, m67));

        if (mx > thr) {   // rare exact path
            float2 hb0 = *(const float2*)&smem.hsb[nw * 64 + p * 16 + tk * 2];
            float2 hb1 = *(const float2*)&smem.hsb[nw * 64 + p * 16 + 8 + tk * 2];
            #pragma unroll
            for (int mt = 0; mt < 2; mt++)
                #pragma unroll
                for (int c = 0; c < 2; c++) {
                    float hbx = c ? hb1.x : hb0.x;
                    float hby = c ? hb1.y : hb0.y;
                    acc[mt][0] += ex2f(fmaf(d[mt][c][0], CC, -(hra[mt][0] + hbx)))
                                + ex2f(fmaf(d[mt][c][1], CC, -(hra[mt][0] + hby)));
                    acc[mt][1] += ex2f(fmaf(d[mt][c][2], CC, -(hra[mt][1] + hbx)))
                                + ex2f(fmaf(d[mt][c][3], CC, -(hra[mt][1] + hby)));
                }
        }
    }

    // ---- reduce across the 4 col-pair lanes; per-(nw) row sums ----
    #pragma unroll
    for (int mt = 0; mt < 2; mt++)
        #pragma unroll
        for (int rr = 0; rr < 2; rr++) {
            float v = acc[mt][rr];
            v += __shfl_xor_sync(~0u, v, 1);
            v += __shfl_xor_sync(~0u, v, 2);
            acc[mt][rr] = v;
        }
    if (tk == 0) {
        #pragma unroll
        for (int mt = 0; mt < 2; mt++) {
            smem.red[nw][mw * 32 + mt * 16 + g]     = acc[mt][0];
            smem.red[nw][mw * 32 + mt * 16 + g + 8] = acc[mt][1];
        }
    }
    __syncthreads();

    if (tid < TM)
        g_scratch[(size_t)(m0 + tid) * NSPLIT + blockIdx.y] =
            smem.red[0][tid] + smem.red[1][tid];

    // ---- last block per m-tile: deterministic final reduction ----
    if (tid == 0) {
        __threadfence();
        int old = atomicAdd(&g_cnt[blockIdx.x], 1);
        is_last = (old == NSPLIT - 1);
        if (is_last) g_cnt[blockIdx.x] = 0;   // reset for graph replay
    }
    __syncthreads();
    if (is_last) {
        __threadfence();
        if (tid < TM) {
            const float4* pr = (const float4*)&g_scratch[(size_t)(m0 + tid) * NSPLIT];
            float s = 0.f;
            #pragma unroll
            for (int j = 0; j < NSPLIT / 4; j++) {   // 8 LDG.128
                float4 v = pr[j];
                s += (v.x + v.y) + (v.z + v.w);
            }
            out[m0 + tid] = s * (9.973557010f / 4096.0f);  // rsqrt(2*pi*var)/N
        }
    }
}

extern "C" void kernel_launch(void* const* d_in, const int* in_sizes, int n_in,
                              void* d_out, int out_size)
{
    const float* test_x  = (const float*)d_in[0];   // [1024,64]
    const float* train_x = (const float*)d_in[1];   // [4096,64]
    float* out = (float*)d_out;                     // [1024]

    kde_prep<<<(MTOT + NTRAIN) * 8 / 256, 256>>>(test_x, train_x);
    dim3 grid(MT, NSPLIT);   // (8,32) = 256 CTAs, one wave @ occ 2
    kde_mma<<<grid, 256>>>(out);
}